// round 1
// baseline (speedup 1.0000x reference)
#include <cuda_runtime.h>
#include <cuda_bf16.h>
#include <math.h>
#include <stdint.h>

#define BATCH 64
#define HD    1024
#define ED    1024
#define VOC   32000
#define TT    50
#define G4    (4*HD)
#define START_IDX 1

// ---------------- device scratch (static: no allocations allowed) ----------------
__device__ __nv_bfloat16 g_emb_hi[VOC*ED];
__device__ __nv_bfloat16 g_emb_lo[VOC*ED];
__device__ __nv_bfloat16 g_Wih_hi[G4*ED];
__device__ __nv_bfloat16 g_Wih_lo[G4*ED];
__device__ __nv_bfloat16 g_Whh_hi[G4*HD];
__device__ __nv_bfloat16 g_Whh_lo[G4*HD];
__device__ __nv_bfloat16 g_Wo_hi[(size_t)VOC*HD];
__device__ __nv_bfloat16 g_Wo_lo[(size_t)VOC*HD];
__device__ __nv_bfloat16 g_hhi[2][BATCH*HD];
__device__ __nv_bfloat16 g_hlo[2][BATCH*HD];
__device__ float g_c[BATCH*HD];
__device__ float g_logits[BATCH*VOC];
__device__ int   g_pred[BATCH];

// ---------------- helpers ----------------
__device__ __forceinline__ void mma16816(float* c,
    uint32_t a0, uint32_t a1, uint32_t a2, uint32_t a3,
    uint32_t b0, uint32_t b1) {
    asm volatile(
        "mma.sync.aligned.m16n8k16.row.col.f32.bf16.bf16.f32 "
        "{%0,%1,%2,%3}, {%4,%5,%6,%7}, {%8,%9}, {%0,%1,%2,%3};\n"
        : "+f"(c[0]), "+f"(c[1]), "+f"(c[2]), "+f"(c[3])
        : "r"(a0), "r"(a1), "r"(a2), "r"(a3), "r"(b0), "r"(b1));
}

// FMA-only exp (for softmax probs only). x <= 0 here. rel err ~1.2e-7.
__device__ __forceinline__ float fast_exp(float x) {
    float t = x * 1.4426950408889634f;      // x * log2(e)
    t = fmaxf(t, -120.0f);
    float n = rintf(t);
    float r = (t - n) * 0.6931471805599453f; // back to natural log domain, |r| <= 0.347
    float p = 1.0f / 5040.0f;
    p = fmaf(p, r, 1.0f / 720.0f);
    p = fmaf(p, r, 1.0f / 120.0f);
    p = fmaf(p, r, 1.0f / 24.0f);
    p = fmaf(p, r, 1.0f / 6.0f);
    p = fmaf(p, r, 0.5f);
    p = fmaf(p, r, 1.0f);
    p = fmaf(p, r, 1.0f);
    float s = __int_as_float(((int)n + 127) << 23);
    return p * s;
}

// ---------------- one-time weight split: w = hi + lo (bf16 planes) ----------------
__global__ void split_kernel(const float* __restrict__ src, int which, int n) {
    __nv_bfloat16 *hi, *lo;
    switch (which) {
        case 0: hi = g_emb_hi; lo = g_emb_lo; break;
        case 1: hi = g_Wih_hi; lo = g_Wih_lo; break;
        case 2: hi = g_Whh_hi; lo = g_Whh_lo; break;
        default: hi = g_Wo_hi; lo = g_Wo_lo; break;
    }
    int i = blockIdx.x * blockDim.x + threadIdx.x;
    int stride = gridDim.x * blockDim.x;
    for (; i < n; i += stride) {
        float w = src[i];
        __nv_bfloat16 h = __float2bfloat16(w);
        hi[i] = h;
        lo[i] = __float2bfloat16(w - __bfloat162float(h));
    }
}

__global__ void init_kernel(const float* __restrict__ hidden) {
    int i = blockIdx.x * blockDim.x + threadIdx.x;
    if (i < BATCH * HD) {
        float h = hidden[i];
        __nv_bfloat16 hh = __float2bfloat16(h);
        g_hhi[0][i] = hh;
        g_hlo[0][i] = __float2bfloat16(h - __bfloat162float(hh));
        g_c[i] = 0.0f;
    }
    if (i < BATCH) g_pred[i] = START_IDX;
}

// ---------------- K1: gates GEMM + LSTM cell ----------------
// block: 8 hidden units -> 32 gate-rows (N=32), M=64 batch, K=2048 ([x ; h])
__global__ __launch_bounds__(256) void gates_kernel(
        const float* __restrict__ b_ih, const float* __restrict__ b_hh,
        int rd, int wb) {
    __shared__ __nv_bfloat16 Ah[64][40], Al[64][40];
    __shared__ __nv_bfloat16 Bh[32][40], Bl[32][40];
    __shared__ float Cs[64][33];
    __shared__ int spred[64];

    const int tid = threadIdx.x;
    const int u0 = blockIdx.x * 8;
    if (tid < 64) spred[tid] = g_pred[tid];
    __syncthreads();

    const int lane = tid & 31, wid = tid >> 5;
    const int gq = lane >> 2, cq = lane & 3;
    const int wm = wid & 3, wn = wid >> 1 & 0; // placeholder (set below)
    const int wnn = wid >> 2;                  // 0..1
    const int arow = tid >> 2;                 // 0..63
    const int klocal = (tid & 3) * 8;

    float acc[2][4];
#pragma unroll
    for (int i = 0; i < 2; i++)
#pragma unroll
        for (int j = 0; j < 4; j++) acc[i][j] = 0.0f;

    const uint32_t* AhW = (const uint32_t*)&Ah[0][0];
    const uint32_t* AlW = (const uint32_t*)&Al[0][0];
    const uint32_t* BhW = (const uint32_t*)&Bh[0][0];
    const uint32_t* BlW = (const uint32_t*)&Bl[0][0];

    for (int kk = 0; kk < 2 * HD; kk += 32) {
        const int kg = kk + klocal;
        {
            const __nv_bfloat16 *sh, *sl;
            if (kg < ED) {
                int e = spred[arow];
                sh = &g_emb_hi[(size_t)e * ED + kg];
                sl = &g_emb_lo[(size_t)e * ED + kg];
            } else {
                sh = &g_hhi[rd][arow * HD + (kg - ED)];
                sl = &g_hlo[rd][arow * HD + (kg - ED)];
            }
            *(uint4*)&Ah[arow][klocal] = *(const uint4*)sh;
            *(uint4*)&Al[arow][klocal] = *(const uint4*)sl;
        }
        if (tid < 128) {
            int n = arow;                       // 0..31
            int row = (n >> 3) * HD + u0 + (n & 7);
            const __nv_bfloat16 *wh, *wl;
            if (kg < ED) {
                wh = &g_Wih_hi[(size_t)row * ED + kg];
                wl = &g_Wih_lo[(size_t)row * ED + kg];
            } else {
                wh = &g_Whh_hi[(size_t)row * HD + (kg - ED)];
                wl = &g_Whh_lo[(size_t)row * HD + (kg - ED)];
            }
            *(uint4*)&Bh[n][klocal] = *(const uint4*)wh;
            *(uint4*)&Bl[n][klocal] = *(const uint4*)wl;
        }
        __syncthreads();

#pragma unroll
        for (int kt = 0; kt < 2; kt++) {
            const int kw = kt * 8 + cq;
            const int m0 = wm * 16 + gq;
            uint32_t ah0 = AhW[m0 * 20 + kw];
            uint32_t ah1 = AhW[(m0 + 8) * 20 + kw];
            uint32_t ah2 = AhW[m0 * 20 + kw + 4];
            uint32_t ah3 = AhW[(m0 + 8) * 20 + kw + 4];
            uint32_t al0 = AlW[m0 * 20 + kw];
            uint32_t al1 = AlW[(m0 + 8) * 20 + kw];
            uint32_t al2 = AlW[m0 * 20 + kw + 4];
            uint32_t al3 = AlW[(m0 + 8) * 20 + kw + 4];
#pragma unroll
            for (int nt = 0; nt < 2; nt++) {
                const int n = wnn * 16 + nt * 8 + gq;
                uint32_t bh0 = BhW[n * 20 + kw], bh1 = BhW[n * 20 + kw + 4];
                uint32_t bl0 = BlW[n * 20 + kw], bl1 = BlW[n * 20 + kw + 4];
                mma16816(acc[nt], ah0, ah1, ah2, ah3, bh0, bh1);
                mma16816(acc[nt], al0, al1, al2, al3, bh0, bh1);
                mma16816(acc[nt], ah0, ah1, ah2, ah3, bl0, bl1);
            }
        }
        __syncthreads();
    }
    (void)wm; (void)wn;

    // stage C into smem so each thread can access all 4 gates of a unit
    {
        const int m0 = wm * 16 + gq;
#pragma unroll
        for (int nt = 0; nt < 2; nt++) {
            const int nc = wnn * 16 + nt * 8 + 2 * cq;
            Cs[m0][nc]       = acc[nt][0];
            Cs[m0][nc + 1]   = acc[nt][1];
            Cs[m0 + 8][nc]     = acc[nt][2];
            Cs[m0 + 8][nc + 1] = acc[nt][3];
        }
    }
    __syncthreads();

    // LSTM cell (gate order i,f,g,o), write c (fp32) and h (bf16 hi/lo ping-pong)
    for (int r = tid; r < 64 * 8; r += 256) {
        const int b = r >> 3, uu = r & 7;
        const int u = u0 + uu;
        float iv = Cs[b][uu]      + b_ih[u]          + b_hh[u];
        float fv = Cs[b][8 + uu]  + b_ih[HD + u]     + b_hh[HD + u];
        float gv = Cs[b][16 + uu] + b_ih[2 * HD + u] + b_hh[2 * HD + u];
        float ov = Cs[b][24 + uu] + b_ih[3 * HD + u] + b_hh[3 * HD + u];
        float co = g_c[b * HD + u];
        float si = 1.0f / (1.0f + expf(-iv));
        float sf = 1.0f / (1.0f + expf(-fv));
        float so = 1.0f / (1.0f + expf(-ov));
        float cn = sf * co + si * tanhf(gv);
        float hn = so * tanhf(cn);
        g_c[b * HD + u] = cn;
        __nv_bfloat16 hh = __float2bfloat16(hn);
        g_hhi[wb][b * HD + u] = hh;
        g_hlo[wb][b * HD + u] = __float2bfloat16(hn - __bfloat162float(hh));
    }
}

// ---------------- K2: logits GEMM (64 x 32000, K=1024), hi/lo 3-term MMA --------
__global__ __launch_bounds__(256) void logits_kernel(
        const float* __restrict__ b_out, int rd) {
    __shared__ __nv_bfloat16 Ah[64][40], Al[64][40];
    __shared__ __nv_bfloat16 Bh[64][40], Bl[64][40];

    const int tid = threadIdx.x;
    const int n0 = blockIdx.x * 64;
    const int lane = tid & 31, wid = tid >> 5;
    const int gq = lane >> 2, cq = lane & 3;
    const int wm = wid & 3, wnn = wid >> 2;   // wm: 0..3 (16 rows), wnn: 0..1 (32 cols)
    const int arow = tid >> 2;
    const int klocal = (tid & 3) * 8;

    float acc[4][4];
#pragma unroll
    for (int i = 0; i < 4; i++)
#pragma unroll
        for (int j = 0; j < 4; j++) acc[i][j] = 0.0f;

    const uint32_t* AhW = (const uint32_t*)&Ah[0][0];
    const uint32_t* AlW = (const uint32_t*)&Al[0][0];
    const uint32_t* BhW = (const uint32_t*)&Bh[0][0];
    const uint32_t* BlW = (const uint32_t*)&Bl[0][0];

    for (int kk = 0; kk < HD; kk += 32) {
        *(uint4*)&Ah[arow][klocal] = *(const uint4*)&g_hhi[rd][arow * HD + kk + klocal];
        *(uint4*)&Al[arow][klocal] = *(const uint4*)&g_hlo[rd][arow * HD + kk + klocal];
        *(uint4*)&Bh[arow][klocal] = *(const uint4*)&g_Wo_hi[(size_t)(n0 + arow) * HD + kk + klocal];
        *(uint4*)&Bl[arow][klocal] = *(const uint4*)&g_Wo_lo[(size_t)(n0 + arow) * HD + kk + klocal];
        __syncthreads();

#pragma unroll
        for (int kt = 0; kt < 2; kt++) {
            const int kw = kt * 8 + cq;
            const int m0 = wm * 16 + gq;
            uint32_t ah0 = AhW[m0 * 20 + kw];
            uint32_t ah1 = AhW[(m0 + 8) * 20 + kw];
            uint32_t ah2 = AhW[m0 * 20 + kw + 4];
            uint32_t ah3 = AhW[(m0 + 8) * 20 + kw + 4];
            uint32_t al0 = AlW[m0 * 20 + kw];
            uint32_t al1 = AlW[(m0 + 8) * 20 + kw];
            uint32_t al2 = AlW[m0 * 20 + kw + 4];
            uint32_t al3 = AlW[(m0 + 8) * 20 + kw + 4];
#pragma unroll
            for (int nt = 0; nt < 4; nt++) {
                const int n = wnn * 32 + nt * 8 + gq;
                uint32_t bh0 = BhW[n * 20 + kw], bh1 = BhW[n * 20 + kw + 4];
                uint32_t bl0 = BlW[n * 20 + kw], bl1 = BlW[n * 20 + kw + 4];
                mma16816(acc[nt], ah0, ah1, ah2, ah3, bh0, bh1);
                mma16816(acc[nt], al0, al1, al2, al3, bh0, bh1);
                mma16816(acc[nt], ah0, ah1, ah2, ah3, bl0, bl1);
            }
        }
        __syncthreads();
    }

    const int m0 = wm * 16 + gq;
#pragma unroll
    for (int nt = 0; nt < 4; nt++) {
        const int nc = n0 + wnn * 32 + nt * 8 + 2 * cq;
        float bo0 = b_out[nc], bo1 = b_out[nc + 1];
        g_logits[m0 * VOC + nc]           = acc[nt][0] + bo0;
        g_logits[m0 * VOC + nc + 1]       = acc[nt][1] + bo1;
        g_logits[(m0 + 8) * VOC + nc]     = acc[nt][2] + bo0;
        g_logits[(m0 + 8) * VOC + nc + 1] = acc[nt][3] + bo1;
    }
}

// ---------------- K3: softmax + argmax + writeback ----------------
__global__ __launch_bounds__(512) void softmax_kernel(float* __restrict__ out, int t, int wp) {
    __shared__ float sv[512];
    __shared__ int   si[512];
    const int b = blockIdx.x;
    const int tid = threadIdx.x;
    float* lrow = g_logits + b * VOC;

    // pass 1: max + first-index argmax
    float m = -1e30f; int mi = VOC;
    for (int v = tid; v < VOC; v += 512) {
        float x = lrow[v];
        if (x > m) { m = x; mi = v; }
    }
    sv[tid] = m; si[tid] = mi;
    __syncthreads();
    for (int s = 256; s > 0; s >>= 1) {
        if (tid < s) {
            float xo = sv[tid + s]; int io = si[tid + s];
            if (xo > sv[tid] || (xo == sv[tid] && io < si[tid])) { sv[tid] = xo; si[tid] = io; }
        }
        __syncthreads();
    }
    const float M = sv[0];
    const int   MI = si[0];
    __syncthreads();

    // pass 2: exp (FMA-only) + sum; stash exp in logits buffer
    float s = 0.0f;
    for (int v = tid; v < VOC; v += 512) {
        float e = fast_exp(lrow[v] - M);
        lrow[v] = e;
        s += e;
    }
    sv[tid] = s;
    __syncthreads();
    for (int st = 256; st > 0; st >>= 1) {
        if (tid < st) sv[tid] += sv[tid + st];
        __syncthreads();
    }
    const float inv = 1.0f / sv[0];

    // pass 3: write probabilities (B, T, V)
    float* orow = out + (size_t)b * TT * VOC + (size_t)t * VOC;
    for (int v = tid; v < VOC; v += 512) orow[v] = lrow[v] * inv;

    if (tid == 0) {
        g_pred[b] = MI;
        if (wp) out[(size_t)BATCH * TT * VOC + (size_t)b * TT + t] = (float)MI;
    }
}

// ---------------- launch ----------------
extern "C" void kernel_launch(void* const* d_in, const int* in_sizes, int n_in,
                              void* d_out, int out_size) {
    const float* hidden = (const float*)d_in[0];
    const float* emb    = (const float*)d_in[1];
    const float* W_ih   = (const float*)d_in[2];
    const float* W_hh   = (const float*)d_in[3];
    const float* b_ih   = (const float*)d_in[4];
    const float* b_hh   = (const float*)d_in[5];
    const float* W_out  = (const float*)d_in[6];
    const float* b_out  = (const float*)d_in[7];
    float* out = (float*)d_out;
    const long long need_pred = (long long)BATCH * TT * VOC + (long long)BATCH * TT;
    int wp = ((long long)out_size >= need_pred) ? 1 : 0;

    init_kernel<<<(BATCH * HD + 255) / 256, 256>>>(hidden);
    split_kernel<<<4096, 256>>>(emb,   0, VOC * ED);
    split_kernel<<<2048, 256>>>(W_ih,  1, G4 * ED);
    split_kernel<<<2048, 256>>>(W_hh,  2, G4 * HD);
    split_kernel<<<4096, 256>>>(W_out, 3, VOC * HD);

    for (int t = 0; t < TT; t++) {
        const int rd = t & 1;
        const int wb = rd ^ 1;
        gates_kernel<<<128, 256>>>(b_ih, b_hh, rd, wb);
        logits_kernel<<<VOC / 64, 256>>>(b_out, wb);
        softmax_kernel<<<BATCH, 512>>>(out, t, wp);
    }
    (void)in_sizes; (void)n_in;
}

// round 2
// speedup vs baseline: 1.1749x; 1.1749x over previous
#include <cuda_runtime.h>
#include <cuda_bf16.h>
#include <math.h>
#include <stdint.h>

#define BATCH 64
#define HD    1024
#define ED    1024
#define VOC   32000
#define TT    50
#define G4    (4*HD)
#define START_IDX 1

// ---------------- device scratch (static: no allocations allowed) ----------------
__device__ __nv_bfloat16 g_emb_hi[VOC*ED];
__device__ __nv_bfloat16 g_emb_lo[VOC*ED];
__device__ __nv_bfloat16 g_Wih_hi[G4*ED];
__device__ __nv_bfloat16 g_Wih_lo[G4*ED];
__device__ __nv_bfloat16 g_Whh_hi[G4*HD];
__device__ __nv_bfloat16 g_Whh_lo[G4*HD];
__device__ __nv_bfloat16 g_Wo_hi[(size_t)VOC*HD];
__device__ __nv_bfloat16 g_Wo_lo[(size_t)VOC*HD];
__device__ __nv_bfloat16 g_hhi[2][BATCH*HD];
__device__ __nv_bfloat16 g_hlo[2][BATCH*HD];
__device__ float g_c[BATCH*HD];
__device__ float g_logits[BATCH*VOC];
__device__ int   g_pred[BATCH];

// ---------------- helpers ----------------
__device__ __forceinline__ void mma16816(float* c,
    uint32_t a0, uint32_t a1, uint32_t a2, uint32_t a3,
    uint32_t b0, uint32_t b1) {
    asm volatile(
        "mma.sync.aligned.m16n8k16.row.col.f32.bf16.bf16.f32 "
        "{%0,%1,%2,%3}, {%4,%5,%6,%7}, {%8,%9}, {%0,%1,%2,%3};\n"
        : "+f"(c[0]), "+f"(c[1]), "+f"(c[2]), "+f"(c[3])
        : "r"(a0), "r"(a1), "r"(a2), "r"(a3), "r"(b0), "r"(b1));
}

__device__ __forceinline__ void cp16(void* smem_dst, const void* gmem_src) {
    uint32_t s = (uint32_t)__cvta_generic_to_shared(smem_dst);
    asm volatile("cp.async.ca.shared.global [%0], [%1], 16;\n" :: "r"(s), "l"(gmem_src));
}
__device__ __forceinline__ void cp_commit() {
    asm volatile("cp.async.commit_group;\n" ::: "memory");
}
__device__ __forceinline__ void cp_wait1() {
    asm volatile("cp.async.wait_group 1;\n" ::: "memory");
}
__device__ __forceinline__ void cp_wait0() {
    asm volatile("cp.async.wait_group 0;\n" ::: "memory");
}

// FMA-only exp (for softmax probs only). x <= 0 here. rel err ~1.2e-7.
__device__ __forceinline__ float fast_exp(float x) {
    float t = x * 1.4426950408889634f;
    t = fmaxf(t, -120.0f);
    float n = rintf(t);
    float r = (t - n) * 0.6931471805599453f;
    float p = 1.0f / 5040.0f;
    p = fmaf(p, r, 1.0f / 720.0f);
    p = fmaf(p, r, 1.0f / 120.0f);
    p = fmaf(p, r, 1.0f / 24.0f);
    p = fmaf(p, r, 1.0f / 6.0f);
    p = fmaf(p, r, 0.5f);
    p = fmaf(p, r, 1.0f);
    p = fmaf(p, r, 1.0f);
    float s = __int_as_float(((int)n + 127) << 23);
    return p * s;
}

// ---------------- one-time weight split: w = hi + lo (bf16 planes) ----------------
__global__ void split_kernel(const float* __restrict__ src, int which, int n) {
    __nv_bfloat16 *hi, *lo;
    switch (which) {
        case 0: hi = g_emb_hi; lo = g_emb_lo; break;
        case 1: hi = g_Wih_hi; lo = g_Wih_lo; break;
        case 2: hi = g_Whh_hi; lo = g_Whh_lo; break;
        default: hi = g_Wo_hi; lo = g_Wo_lo; break;
    }
    int i = blockIdx.x * blockDim.x + threadIdx.x;
    int stride = gridDim.x * blockDim.x;
    for (; i < n; i += stride) {
        float w = src[i];
        __nv_bfloat16 h = __float2bfloat16(w);
        hi[i] = h;
        lo[i] = __float2bfloat16(w - __bfloat162float(h));
    }
}

__global__ void init_kernel(const float* __restrict__ hidden) {
    int i = blockIdx.x * blockDim.x + threadIdx.x;
    if (i < BATCH * HD) {
        float h = hidden[i];
        __nv_bfloat16 hh = __float2bfloat16(h);
        g_hhi[0][i] = hh;
        g_hlo[0][i] = __float2bfloat16(h - __bfloat162float(hh));
        g_c[i] = 0.0f;
    }
    if (i < BATCH) g_pred[i] = START_IDX;
}

// ---------------- K1: gates GEMM + LSTM cell (cp.async double-buffered) ----------
// block: 8 hidden units -> 32 gate-rows (N=32), M=64 batch, K=2048 ([x ; h])
__global__ __launch_bounds__(256) void gates_kernel(
        const float* __restrict__ b_ih, const float* __restrict__ b_hh,
        int rd, int wb) {
    __shared__ __nv_bfloat16 Ah[2][64][40], Al[2][64][40];
    __shared__ __nv_bfloat16 Bh[2][32][40], Bl[2][32][40];
    __shared__ float Cs[64][33];
    __shared__ int spred[64];

    const int tid = threadIdx.x;
    const int u0 = blockIdx.x * 8;
    if (tid < 64) spred[tid] = g_pred[tid];
    __syncthreads();

    const int lane = tid & 31, wid = tid >> 5;
    const int gq = lane >> 2, cq = lane & 3;
    const int wm = wid & 3;
    const int wnn = wid >> 2;                  // 0..1
    const int arow = tid >> 2;                 // 0..63
    const int aseg = (tid & 3) * 8;            // halves offset (8 halves = 16B)

    // B-row mapping: gate-major (i,f,g,o x 8 units)
    const int bn   = tid >> 3;                 // 0..31 (for tid<256 -> covers twice; use tid<128 set)
    const int bseg = (tid & 7) * 0;            // unused placeholder
    (void)bn; (void)bseg;

    float acc[2][4];
#pragma unroll
    for (int i = 0; i < 2; i++)
#pragma unroll
        for (int j = 0; j < 4; j++) acc[i][j] = 0.0f;

    // --- async load issuer for K-chunk "ck" (32 halves) into buffer "buf" ---
    auto issue = [&](int ck, int buf) {
        const int kg = ck * 32 + aseg;
        // A: 64 rows x (4 x 16B), one 16B per thread per plane
        {
            const __nv_bfloat16 *sh, *sl;
            if (kg < ED) {
                int e = spred[arow];
                sh = &g_emb_hi[(size_t)e * ED + kg];
                sl = &g_emb_lo[(size_t)e * ED + kg];
            } else {
                sh = &g_hhi[rd][arow * HD + (kg - ED)];
                sl = &g_hlo[rd][arow * HD + (kg - ED)];
            }
            cp16(&Ah[buf][arow][aseg], sh);
            cp16(&Al[buf][arow][aseg], sl);
        }
        // B: 32 rows x (4 x 16B), threads 0..127
        if (tid < 128) {
            const int n = tid >> 2;             // 0..31
            const int seg = (tid & 3) * 8;
            const int kgb = ck * 32 + seg;
            const int row = (n >> 3) * HD + u0 + (n & 7);
            const __nv_bfloat16 *wh, *wl;
            if (kgb < ED) {
                wh = &g_Wih_hi[(size_t)row * ED + kgb];
                wl = &g_Wih_lo[(size_t)row * ED + kgb];
            } else {
                wh = &g_Whh_hi[(size_t)row * HD + (kgb - ED)];
                wl = &g_Whh_lo[(size_t)row * HD + (kgb - ED)];
            }
            cp16(&Bh[buf][n][seg], wh);
            cp16(&Bl[buf][n][seg], wl);
        }
    };

    const int NIT = (2 * HD) / 32;   // 64
    issue(0, 0);
    cp_commit();

    for (int it = 0; it < NIT; it++) {
        if (it + 1 < NIT) {
            issue(it + 1, (it + 1) & 1);
            cp_commit();
            cp_wait1();
        } else {
            cp_wait0();
        }
        __syncthreads();

        const int buf = it & 1;
        const uint32_t* AhW = (const uint32_t*)&Ah[buf][0][0];
        const uint32_t* AlW = (const uint32_t*)&Al[buf][0][0];
        const uint32_t* BhW = (const uint32_t*)&Bh[buf][0][0];
        const uint32_t* BlW = (const uint32_t*)&Bl[buf][0][0];

#pragma unroll
        for (int kt = 0; kt < 2; kt++) {
            const int kw = kt * 8 + cq;
            const int m0 = wm * 16 + gq;
            uint32_t ah0 = AhW[m0 * 20 + kw];
            uint32_t ah1 = AhW[(m0 + 8) * 20 + kw];
            uint32_t ah2 = AhW[m0 * 20 + kw + 4];
            uint32_t ah3 = AhW[(m0 + 8) * 20 + kw + 4];
            uint32_t al0 = AlW[m0 * 20 + kw];
            uint32_t al1 = AlW[(m0 + 8) * 20 + kw];
            uint32_t al2 = AlW[m0 * 20 + kw + 4];
            uint32_t al3 = AlW[(m0 + 8) * 20 + kw + 4];
#pragma unroll
            for (int nt = 0; nt < 2; nt++) {
                const int n = wnn * 16 + nt * 8 + gq;
                uint32_t bh0 = BhW[n * 20 + kw], bh1 = BhW[n * 20 + kw + 4];
                uint32_t bl0 = BlW[n * 20 + kw], bl1 = BlW[n * 20 + kw + 4];
                mma16816(acc[nt], ah0, ah1, ah2, ah3, bh0, bh1);
                mma16816(acc[nt], al0, al1, al2, al3, bh0, bh1);
                mma16816(acc[nt], ah0, ah1, ah2, ah3, bl0, bl1);
            }
        }
        __syncthreads();
    }

    // stage C into smem so each thread can access all 4 gates of a unit
    {
        const int m0 = wm * 16 + gq;
#pragma unroll
        for (int nt = 0; nt < 2; nt++) {
            const int nc = wnn * 16 + nt * 8 + 2 * cq;
            Cs[m0][nc]         = acc[nt][0];
            Cs[m0][nc + 1]     = acc[nt][1];
            Cs[m0 + 8][nc]     = acc[nt][2];
            Cs[m0 + 8][nc + 1] = acc[nt][3];
        }
    }
    __syncthreads();

    // LSTM cell (gate order i,f,g,o), write c (fp32) and h (bf16 hi/lo ping-pong)
    for (int r = tid; r < 64 * 8; r += 256) {
        const int b = r >> 3, uu = r & 7;
        const int u = u0 + uu;
        float iv = Cs[b][uu]      + b_ih[u]          + b_hh[u];
        float fv = Cs[b][8 + uu]  + b_ih[HD + u]     + b_hh[HD + u];
        float gv = Cs[b][16 + uu] + b_ih[2 * HD + u] + b_hh[2 * HD + u];
        float ov = Cs[b][24 + uu] + b_ih[3 * HD + u] + b_hh[3 * HD + u];
        float co = g_c[b * HD + u];
        float si = 1.0f / (1.0f + expf(-iv));
        float sf = 1.0f / (1.0f + expf(-fv));
        float so = 1.0f / (1.0f + expf(-ov));
        float cn = sf * co + si * tanhf(gv);
        float hn = so * tanhf(cn);
        g_c[b * HD + u] = cn;
        __nv_bfloat16 hh = __float2bfloat16(hn);
        g_hhi[wb][b * HD + u] = hh;
        g_hlo[wb][b * HD + u] = __float2bfloat16(hn - __bfloat162float(hh));
    }
}

// ---------------- K2: logits GEMM (64 x 32000, K=1024), cp.async pipelined ------
__global__ __launch_bounds__(256) void logits_kernel(
        const float* __restrict__ b_out, int rd) {
    __shared__ __nv_bfloat16 Ah[2][64][40], Al[2][64][40];
    __shared__ __nv_bfloat16 Bh[2][64][40], Bl[2][64][40];

    const int tid = threadIdx.x;
    const int n0 = blockIdx.x * 64;
    const int lane = tid & 31, wid = tid >> 5;
    const int gq = lane >> 2, cq = lane & 3;
    const int wm = wid & 3, wnn = wid >> 2;   // wm: 0..3 (16 rows), wnn: 0..1 (32 cols)
    const int arow = tid >> 2;                // 0..63
    const int aseg = (tid & 3) * 8;           // halves (16B)

    float acc[4][4];
#pragma unroll
    for (int i = 0; i < 4; i++)
#pragma unroll
        for (int j = 0; j < 4; j++) acc[i][j] = 0.0f;

    auto issue = [&](int ck, int buf) {
        const int kg = ck * 32 + aseg;
        cp16(&Ah[buf][arow][aseg], &g_hhi[rd][arow * HD + kg]);
        cp16(&Al[buf][arow][aseg], &g_hlo[rd][arow * HD + kg]);
        cp16(&Bh[buf][arow][aseg], &g_Wo_hi[(size_t)(n0 + arow) * HD + kg]);
        cp16(&Bl[buf][arow][aseg], &g_Wo_lo[(size_t)(n0 + arow) * HD + kg]);
    };

    const int NIT = HD / 32;   // 32
    issue(0, 0);
    cp_commit();

    for (int it = 0; it < NIT; it++) {
        if (it + 1 < NIT) {
            issue(it + 1, (it + 1) & 1);
            cp_commit();
            cp_wait1();
        } else {
            cp_wait0();
        }
        __syncthreads();

        const int buf = it & 1;
        const uint32_t* AhW = (const uint32_t*)&Ah[buf][0][0];
        const uint32_t* AlW = (const uint32_t*)&Al[buf][0][0];
        const uint32_t* BhW = (const uint32_t*)&Bh[buf][0][0];
        const uint32_t* BlW = (const uint32_t*)&Bl[buf][0][0];

#pragma unroll
        for (int kt = 0; kt < 2; kt++) {
            const int kw = kt * 8 + cq;
            const int m0 = wm * 16 + gq;
            uint32_t ah0 = AhW[m0 * 20 + kw];
            uint32_t ah1 = AhW[(m0 + 8) * 20 + kw];
            uint32_t ah2 = AhW[m0 * 20 + kw + 4];
            uint32_t ah3 = AhW[(m0 + 8) * 20 + kw + 4];
            uint32_t al0 = AlW[m0 * 20 + kw];
            uint32_t al1 = AlW[(m0 + 8) * 20 + kw];
            uint32_t al2 = AlW[m0 * 20 + kw + 4];
            uint32_t al3 = AlW[(m0 + 8) * 20 + kw + 4];
#pragma unroll
            for (int nt = 0; nt < 4; nt++) {
                const int n = wnn * 32 + nt * 8 + gq;
                uint32_t bh0 = BhW[n * 20 + kw], bh1 = BhW[n * 20 + kw + 4];
                uint32_t bl0 = BlW[n * 20 + kw], bl1 = BlW[n * 20 + kw + 4];
                mma16816(acc[nt], ah0, ah1, ah2, ah3, bh0, bh1);
                mma16816(acc[nt], al0, al1, al2, al3, bh0, bh1);
                mma16816(acc[nt], ah0, ah1, ah2, ah3, bl0, bl1);
            }
        }
        __syncthreads();
    }

    const int m0 = wm * 16 + gq;
#pragma unroll
    for (int nt = 0; nt < 4; nt++) {
        const int nc = n0 + wnn * 32 + nt * 8 + 2 * cq;
        float bo0 = b_out[nc], bo1 = b_out[nc + 1];
        g_logits[m0 * VOC + nc]           = acc[nt][0] + bo0;
        g_logits[m0 * VOC + nc + 1]       = acc[nt][1] + bo1;
        g_logits[(m0 + 8) * VOC + nc]     = acc[nt][2] + bo0;
        g_logits[(m0 + 8) * VOC + nc + 1] = acc[nt][3] + bo1;
    }
}

// ---------------- K3: online softmax + argmax + writeback ----------------
__global__ __launch_bounds__(1024) void softmax_kernel(float* __restrict__ out, int t, int wp) {
    __shared__ float sm[1024];
    __shared__ float ss[1024];
    __shared__ int   si[1024];
    const int b = blockIdx.x;
    const int tid = threadIdx.x;
    const float* lrow = g_logits + b * VOC;

    // pass 1: online max + sum + first-index argmax
    float m = -1e30f, s = 0.0f; int mi = VOC;
    for (int v = tid; v < VOC; v += 1024) {
        float x = lrow[v];
        if (x > m) {
            s = fmaf(s, fast_exp(m - x), 1.0f);
            m = x; mi = v;
        } else {
            s += fast_exp(x - m);
        }
    }
    sm[tid] = m; ss[tid] = s; si[tid] = mi;
    __syncthreads();
    for (int st = 512; st > 0; st >>= 1) {
        if (tid < st) {
            float mo = sm[tid + st], so = ss[tid + st]; int io = si[tid + st];
            float mc = sm[tid],     sc = ss[tid];       int ic = si[tid];
            if (mo > mc || (mo == mc && io < ic)) {
                sm[tid] = mo;
                ss[tid] = fmaf(sc, fast_exp(mc - mo), so);
                si[tid] = io;
            } else {
                ss[tid] = fmaf(so, fast_exp(mo - mc), sc);
            }
        }
        __syncthreads();
    }
    const float M = sm[0];
    const int   MI = si[0];
    const float inv = 1.0f / ss[0];

    // pass 2: write probabilities (B, T, V)
    float* orow = out + (size_t)b * TT * VOC + (size_t)t * VOC;
    for (int v = tid; v < VOC; v += 1024) orow[v] = fast_exp(lrow[v] - M) * inv;

    if (tid == 0) {
        g_pred[b] = MI;
        if (wp) out[(size_t)BATCH * TT * VOC + (size_t)b * TT + t] = (float)MI;
    }
}

// ---------------- launch ----------------
extern "C" void kernel_launch(void* const* d_in, const int* in_sizes, int n_in,
                              void* d_out, int out_size) {
    const float* hidden = (const float*)d_in[0];
    const float* emb    = (const float*)d_in[1];
    const float* W_ih   = (const float*)d_in[2];
    const float* W_hh   = (const float*)d_in[3];
    const float* b_ih   = (const float*)d_in[4];
    const float* b_hh   = (const float*)d_in[5];
    const float* W_out  = (const float*)d_in[6];
    const float* b_out  = (const float*)d_in[7];
    float* out = (float*)d_out;
    const long long need_pred = (long long)BATCH * TT * VOC + (long long)BATCH * TT;
    int wp = ((long long)out_size >= need_pred) ? 1 : 0;

    init_kernel<<<(BATCH * HD + 255) / 256, 256>>>(hidden);
    split_kernel<<<4096, 256>>>(emb,   0, VOC * ED);
    split_kernel<<<2048, 256>>>(W_ih,  1, G4 * ED);
    split_kernel<<<2048, 256>>>(W_hh,  2, G4 * HD);
    split_kernel<<<4096, 256>>>(W_out, 3, VOC * HD);

    for (int t = 0; t < TT; t++) {
        const int rd = t & 1;
        const int wb = rd ^ 1;
        gates_kernel<<<128, 256>>>(b_ih, b_hh, rd, wb);
        logits_kernel<<<VOC / 64, 256>>>(b_out, wb);
        softmax_kernel<<<BATCH, 1024>>>(out, t, wp);
    }
    (void)in_sizes; (void)n_in;
}

// round 3
// speedup vs baseline: 1.7060x; 1.4520x over previous
#include <cuda_runtime.h>
#include <cuda_bf16.h>
#include <cuda_fp16.h>
#include <math.h>
#include <stdint.h>

#define BATCH 64
#define HD    1024
#define ED    1024
#define VOC   32000
#define TT    50
#define G4    (4*HD)
#define START_IDX 1

// ---------------- device scratch ----------------
__device__ __nv_bfloat16 g_emb_hi[VOC*ED];
__device__ __nv_bfloat16 g_emb_lo[VOC*ED];
__device__ __nv_bfloat16 g_Wih_hi[G4*ED];
__device__ __nv_bfloat16 g_Wih_lo[G4*ED];
__device__ __nv_bfloat16 g_Whh_hi[G4*HD];
__device__ __nv_bfloat16 g_Whh_lo[G4*HD];
__device__ __half        g_Wo16[(size_t)VOC*HD];
__device__ __nv_bfloat16 g_hhi[2][BATCH*HD];
__device__ __nv_bfloat16 g_hlo[2][BATCH*HD];
__device__ __half        g_h16[2][BATCH*HD];
__device__ float g_c[BATCH*HD];
__device__ float g_logits[BATCH*VOC];
__device__ int   g_pred[BATCH];

// ---------------- helpers ----------------
__device__ __forceinline__ void mma16816bf(float* c,
    uint32_t a0, uint32_t a1, uint32_t a2, uint32_t a3,
    uint32_t b0, uint32_t b1) {
    asm volatile(
        "mma.sync.aligned.m16n8k16.row.col.f32.bf16.bf16.f32 "
        "{%0,%1,%2,%3}, {%4,%5,%6,%7}, {%8,%9}, {%0,%1,%2,%3};\n"
        : "+f"(c[0]), "+f"(c[1]), "+f"(c[2]), "+f"(c[3])
        : "r"(a0), "r"(a1), "r"(a2), "r"(a3), "r"(b0), "r"(b1));
}
__device__ __forceinline__ void mma16816f16(float* c,
    uint32_t a0, uint32_t a1, uint32_t a2, uint32_t a3,
    uint32_t b0, uint32_t b1) {
    asm volatile(
        "mma.sync.aligned.m16n8k16.row.col.f32.f16.f16.f32 "
        "{%0,%1,%2,%3}, {%4,%5,%6,%7}, {%8,%9}, {%0,%1,%2,%3};\n"
        : "+f"(c[0]), "+f"(c[1]), "+f"(c[2]), "+f"(c[3])
        : "r"(a0), "r"(a1), "r"(a2), "r"(a3), "r"(b0), "r"(b1));
}

__device__ __forceinline__ void cp16(void* smem_dst, const void* gmem_src) {
    uint32_t s = (uint32_t)__cvta_generic_to_shared(smem_dst);
    asm volatile("cp.async.ca.shared.global [%0], [%1], 16;\n" :: "r"(s), "l"(gmem_src));
}
__device__ __forceinline__ void cp_commit() { asm volatile("cp.async.commit_group;\n" ::: "memory"); }
__device__ __forceinline__ void cp_wait1()  { asm volatile("cp.async.wait_group 1;\n" ::: "memory"); }
__device__ __forceinline__ void cp_wait0()  { asm volatile("cp.async.wait_group 0;\n" ::: "memory"); }

// FMA-only exp. rel err ~1.2e-7 for x<=0.
__device__ __forceinline__ float fast_exp(float x) {
    float t = x * 1.4426950408889634f;
    t = fmaxf(t, -120.0f);
    float n = rintf(t);
    float r = (t - n) * 0.6931471805599453f;
    float p = 1.0f / 5040.0f;
    p = fmaf(p, r, 1.0f / 720.0f);
    p = fmaf(p, r, 1.0f / 120.0f);
    p = fmaf(p, r, 1.0f / 24.0f);
    p = fmaf(p, r, 1.0f / 6.0f);
    p = fmaf(p, r, 0.5f);
    p = fmaf(p, r, 1.0f);
    p = fmaf(p, r, 1.0f);
    float s = __int_as_float(((int)n + 127) << 23);
    return p * s;
}

// ---------------- one-time weight prep ----------------
__global__ void split_kernel(const float* __restrict__ src, int which, int n) {
    int i = blockIdx.x * blockDim.x + threadIdx.x;
    int stride = gridDim.x * blockDim.x;
    if (which == 3) {
        for (; i < n; i += stride) g_Wo16[i] = __float2half(src[i]);
        return;
    }
    __nv_bfloat16 *hi, *lo;
    switch (which) {
        case 0: hi = g_emb_hi; lo = g_emb_lo; break;
        case 1: hi = g_Wih_hi; lo = g_Wih_lo; break;
        default: hi = g_Whh_hi; lo = g_Whh_lo; break;
    }
    for (; i < n; i += stride) {
        float w = src[i];
        __nv_bfloat16 h = __float2bfloat16(w);
        hi[i] = h;
        lo[i] = __float2bfloat16(w - __bfloat162float(h));
    }
}

__global__ void init_kernel(const float* __restrict__ hidden) {
    int i = blockIdx.x * blockDim.x + threadIdx.x;
    if (i < BATCH * HD) {
        float h = hidden[i];
        __nv_bfloat16 hh = __float2bfloat16(h);
        g_hhi[0][i] = hh;
        g_hlo[0][i] = __float2bfloat16(h - __bfloat162float(hh));
        g_c[i] = 0.0f;
    }
    if (i < BATCH) g_pred[i] = START_IDX;
}

// ---------------- K1: gates GEMM + LSTM cell (2-stage cp.async) ----------
__global__ __launch_bounds__(256) void gates_kernel(
        const float* __restrict__ b_ih, const float* __restrict__ b_hh,
        int rd, int wb) {
    __shared__ __nv_bfloat16 Ah[2][64][40], Al[2][64][40];
    __shared__ __nv_bfloat16 Bh[2][32][40], Bl[2][32][40];
    __shared__ float Cs[64][33];
    __shared__ int spred[64];

    const int tid = threadIdx.x;
    const int u0 = blockIdx.x * 8;
    if (tid < 64) spred[tid] = g_pred[tid];
    __syncthreads();

    const int lane = tid & 31, wid = tid >> 5;
    const int gq = lane >> 2, cq = lane & 3;
    const int wm = wid & 3;
    const int wnn = wid >> 2;
    const int arow = tid >> 2;
    const int aseg = (tid & 3) * 8;

    float acc[2][4];
#pragma unroll
    for (int i = 0; i < 2; i++)
#pragma unroll
        for (int j = 0; j < 4; j++) acc[i][j] = 0.0f;

    auto issue = [&](int ck, int buf) {
        const int kg = ck * 32 + aseg;
        {
            const __nv_bfloat16 *sh, *sl;
            if (kg < ED) {
                int e = spred[arow];
                sh = &g_emb_hi[(size_t)e * ED + kg];
                sl = &g_emb_lo[(size_t)e * ED + kg];
            } else {
                sh = &g_hhi[rd][arow * HD + (kg - ED)];
                sl = &g_hlo[rd][arow * HD + (kg - ED)];
            }
            cp16(&Ah[buf][arow][aseg], sh);
            cp16(&Al[buf][arow][aseg], sl);
        }
        if (tid < 128) {
            const int n = tid >> 2;
            const int seg = (tid & 3) * 8;
            const int kgb = ck * 32 + seg;
            const int row = (n >> 3) * HD + u0 + (n & 7);
            const __nv_bfloat16 *wh, *wl;
            if (kgb < ED) {
                wh = &g_Wih_hi[(size_t)row * ED + kgb];
                wl = &g_Wih_lo[(size_t)row * ED + kgb];
            } else {
                wh = &g_Whh_hi[(size_t)row * HD + (kgb - ED)];
                wl = &g_Whh_lo[(size_t)row * HD + (kgb - ED)];
            }
            cp16(&Bh[buf][n][seg], wh);
            cp16(&Bl[buf][n][seg], wl);
        }
    };

    const int NIT = (2 * HD) / 32;
    issue(0, 0);
    cp_commit();

    for (int it = 0; it < NIT; it++) {
        if (it + 1 < NIT) {
            issue(it + 1, (it + 1) & 1);
            cp_commit();
            cp_wait1();
        } else {
            cp_wait0();
        }
        __syncthreads();

        const int buf = it & 1;
        const uint32_t* AhW = (const uint32_t*)&Ah[buf][0][0];
        const uint32_t* AlW = (const uint32_t*)&Al[buf][0][0];
        const uint32_t* BhW = (const uint32_t*)&Bh[buf][0][0];
        const uint32_t* BlW = (const uint32_t*)&Bl[buf][0][0];

#pragma unroll
        for (int kt = 0; kt < 2; kt++) {
            const int kw = kt * 8 + cq;
            const int m0 = wm * 16 + gq;
            uint32_t ah0 = AhW[m0 * 20 + kw];
            uint32_t ah1 = AhW[(m0 + 8) * 20 + kw];
            uint32_t ah2 = AhW[m0 * 20 + kw + 4];
            uint32_t ah3 = AhW[(m0 + 8) * 20 + kw + 4];
            uint32_t al0 = AlW[m0 * 20 + kw];
            uint32_t al1 = AlW[(m0 + 8) * 20 + kw];
            uint32_t al2 = AlW[m0 * 20 + kw + 4];
            uint32_t al3 = AlW[(m0 + 8) * 20 + kw + 4];
#pragma unroll
            for (int nt = 0; nt < 2; nt++) {
                const int n = wnn * 16 + nt * 8 + gq;
                uint32_t bh0 = BhW[n * 20 + kw], bh1 = BhW[n * 20 + kw + 4];
                uint32_t bl0 = BlW[n * 20 + kw], bl1 = BlW[n * 20 + kw + 4];
                mma16816bf(acc[nt], ah0, ah1, ah2, ah3, bh0, bh1);
                mma16816bf(acc[nt], al0, al1, al2, al3, bh0, bh1);
                mma16816bf(acc[nt], ah0, ah1, ah2, ah3, bl0, bl1);
            }
        }
        __syncthreads();
    }

    {
        const int m0 = wm * 16 + gq;
#pragma unroll
        for (int nt = 0; nt < 2; nt++) {
            const int nc = wnn * 16 + nt * 8 + 2 * cq;
            Cs[m0][nc]         = acc[nt][0];
            Cs[m0][nc + 1]     = acc[nt][1];
            Cs[m0 + 8][nc]     = acc[nt][2];
            Cs[m0 + 8][nc + 1] = acc[nt][3];
        }
    }
    __syncthreads();

    for (int r = tid; r < 64 * 8; r += 256) {
        const int b = r >> 3, uu = r & 7;
        const int u = u0 + uu;
        float iv = Cs[b][uu]      + b_ih[u]          + b_hh[u];
        float fv = Cs[b][8 + uu]  + b_ih[HD + u]     + b_hh[HD + u];
        float gv = Cs[b][16 + uu] + b_ih[2 * HD + u] + b_hh[2 * HD + u];
        float ov = Cs[b][24 + uu] + b_ih[3 * HD + u] + b_hh[3 * HD + u];
        float co = g_c[b * HD + u];
        float si = 1.0f / (1.0f + expf(-iv));
        float sf = 1.0f / (1.0f + expf(-fv));
        float so = 1.0f / (1.0f + expf(-ov));
        float cn = sf * co + si * tanhf(gv);
        float hn = so * tanhf(cn);
        g_c[b * HD + u] = cn;
        __nv_bfloat16 hh = __float2bfloat16(hn);
        g_hhi[wb][b * HD + u] = hh;
        g_hlo[wb][b * HD + u] = __float2bfloat16(hn - __bfloat162float(hh));
        g_h16[wb][b * HD + u] = __float2half(hn);
    }
}

// ---------------- K2: logits GEMM 64 x 32000, K=1024, fp16 single-plane ----------
// N=128 per block (250 blocks), 3-stage cp.async pipeline.
__global__ __launch_bounds__(256) void logits_kernel(
        const float* __restrict__ b_out, int rd) {
    __shared__ __half Aa[3][64][40];
    __shared__ __half Bb[3][128][40];

    const int tid = threadIdx.x;
    const int n0 = blockIdx.x * 128;
    const int lane = tid & 31, wid = tid >> 5;
    const int gq = lane >> 2, cq = lane & 3;
    const int wm = wid & 3, wn = wid >> 2;     // wm: 16-row group, wn: 64-col half
    const int arow = tid >> 2;                 // 0..63
    const int aseg = (tid & 3) * 8;

    float acc[8][4];
#pragma unroll
    for (int i = 0; i < 8; i++)
#pragma unroll
        for (int j = 0; j < 4; j++) acc[i][j] = 0.0f;

    auto issue = [&](int ck, int buf) {
        const int kg = ck * 32;
        cp16(&Aa[buf][arow][aseg], &g_h16[rd][arow * HD + kg + aseg]);
#pragma unroll
        for (int l = 0; l < 2; l++) {
            const int idx = tid + l * 256;
            const int row = idx >> 2;           // 0..127
            const int seg = (idx & 3) * 8;
            cp16(&Bb[buf][row][seg], &g_Wo16[(size_t)(n0 + row) * HD + kg + seg]);
        }
    };

    const int NIT = HD / 32;   // 32
    issue(0, 0); cp_commit();
    issue(1, 1); cp_commit();

    for (int it = 0; it < NIT; it++) {
        if (it + 1 < NIT) cp_wait1(); else cp_wait0();
        __syncthreads();
        if (it + 2 < NIT) { issue(it + 2, (it + 2) % 3); cp_commit(); }

        const int buf = it % 3;
        const uint32_t* AW = (const uint32_t*)&Aa[buf][0][0];
        const uint32_t* BW = (const uint32_t*)&Bb[buf][0][0];

#pragma unroll
        for (int kt = 0; kt < 2; kt++) {
            const int kw = kt * 8 + cq;
            const int m0 = wm * 16 + gq;
            uint32_t a0 = AW[m0 * 20 + kw];
            uint32_t a1 = AW[(m0 + 8) * 20 + kw];
            uint32_t a2 = AW[m0 * 20 + kw + 4];
            uint32_t a3 = AW[(m0 + 8) * 20 + kw + 4];
#pragma unroll
            for (int nt = 0; nt < 8; nt++) {
                const int n = wn * 64 + nt * 8 + gq;
                uint32_t b0 = BW[n * 20 + kw], b1 = BW[n * 20 + kw + 4];
                mma16816f16(acc[nt], a0, a1, a2, a3, b0, b1);
            }
        }
    }

    const int m0 = wm * 16 + gq;
#pragma unroll
    for (int nt = 0; nt < 8; nt++) {
        const int nc = n0 + wn * 64 + nt * 8 + 2 * cq;
        float bo0 = b_out[nc], bo1 = b_out[nc + 1];
        g_logits[m0 * VOC + nc]           = acc[nt][0] + bo0;
        g_logits[m0 * VOC + nc + 1]       = acc[nt][1] + bo1;
        g_logits[(m0 + 8) * VOC + nc]     = acc[nt][2] + bo0;
        g_logits[(m0 + 8) * VOC + nc + 1] = acc[nt][3] + bo1;
    }
}

// ---------------- K3: softmax + candidate argmax + exact rescue ----------------
__global__ __launch_bounds__(1024) void softmax_kernel(
        float* __restrict__ out, const float* __restrict__ Wout,
        const float* __restrict__ b_out, int t, int wp, int rd) {
    __shared__ float sm_[1024];
    __shared__ float ss_[1024];
    __shared__ float red[32];
    __shared__ float hbuf[1024];
    __shared__ int cand[64];
    __shared__ int ncand;
    const int b = blockIdx.x;
    const int tid = threadIdx.x;
    const int lane = tid & 31, wid = tid >> 5;
    const float* lrow = g_logits + b * VOC;

    if (tid == 0) ncand = 0;

    // online max + sum
    float m = -1e30f, s = 0.0f;
    for (int v = tid; v < VOC; v += 1024) {
        float x = lrow[v];
        if (x > m) { s = fmaf(s, fast_exp(m - x), 1.0f); m = x; }
        else s += fast_exp(x - m);
    }
    sm_[tid] = m; ss_[tid] = s;
    __syncthreads();
    for (int st = 512; st > 0; st >>= 1) {
        if (tid < st) {
            float mo = sm_[tid + st], so = ss_[tid + st];
            float mc = sm_[tid],      sc = ss_[tid];
            if (mo > mc) { sm_[tid] = mo; ss_[tid] = fmaf(sc, fast_exp(mc - mo), so); }
            else         { ss_[tid] = fmaf(so, fast_exp(mo - mc), sc); }
        }
        __syncthreads();
    }
    const float M = sm_[0];
    const float inv = 1.0f / ss_[0];
    const float thresh = M - 0.01f;
    __syncthreads();

    // write probs + collect argmax candidates
    float* orow = out + (size_t)b * TT * VOC + (size_t)t * VOC;
    for (int v = tid; v < VOC; v += 1024) {
        float x = lrow[v];
        orow[v] = fast_exp(x - M) * inv;
        if (x > thresh) {
            int p = atomicAdd(&ncand, 1);
            if (p < 64) cand[p] = v;
        }
    }

    // accurate h for exact rescoring
    hbuf[tid] = __bfloat162float(g_hhi[rd][b * HD + tid]) +
                __bfloat162float(g_hlo[rd][b * HD + tid]);
    __syncthreads();

    const int nc = min(ncand, 64);
    float bestv = -1e30f;
    int   besti = VOC;
    for (int i = 0; i < nc; i++) {
        const int v = cand[i];
        float part = hbuf[tid] * Wout[(size_t)v * HD + tid];
#pragma unroll
        for (int o = 16; o > 0; o >>= 1) part += __shfl_xor_sync(0xFFFFFFFFu, part, o);
        if (lane == 0) red[wid] = part;
        __syncthreads();
        if (tid < 32) {
            float pv = red[tid];
#pragma unroll
            for (int o = 16; o > 0; o >>= 1) pv += __shfl_xor_sync(0xFFFFFFFFu, pv, o);
            if (tid == 0) {
                float lg = pv + b_out[v];
                if (lg > bestv || (lg == bestv && v < besti)) { bestv = lg; besti = v; }
            }
        }
        __syncthreads();
    }

    if (tid == 0) {
        g_pred[b] = besti;
        if (wp) out[(size_t)BATCH * TT * VOC + (size_t)b * TT + t] = (float)besti;
    }
}

// ---------------- launch ----------------
extern "C" void kernel_launch(void* const* d_in, const int* in_sizes, int n_in,
                              void* d_out, int out_size) {
    const float* hidden = (const float*)d_in[0];
    const float* emb    = (const float*)d_in[1];
    const float* W_ih   = (const float*)d_in[2];
    const float* W_hh   = (const float*)d_in[3];
    const float* b_ih   = (const float*)d_in[4];
    const float* b_hh   = (const float*)d_in[5];
    const float* W_out  = (const float*)d_in[6];
    const float* b_out  = (const float*)d_in[7];
    float* out = (float*)d_out;
    const long long need_pred = (long long)BATCH * TT * VOC + (long long)BATCH * TT;
    int wp = ((long long)out_size >= need_pred) ? 1 : 0;

    init_kernel<<<(BATCH * HD + 255) / 256, 256>>>(hidden);
    split_kernel<<<4096, 256>>>(emb,   0, VOC * ED);
    split_kernel<<<2048, 256>>>(W_ih,  1, G4 * ED);
    split_kernel<<<2048, 256>>>(W_hh,  2, G4 * HD);
    split_kernel<<<4096, 256>>>(W_out, 3, VOC * HD);

    for (int t = 0; t < TT; t++) {
        const int rd = t & 1;
        const int wb = rd ^ 1;
        gates_kernel<<<128, 256>>>(b_ih, b_hh, rd, wb);
        logits_kernel<<<250, 256>>>(b_out, wb);
        softmax_kernel<<<BATCH, 1024>>>(out, W_out, b_out, t, wp, wb);
    }
    (void)in_sizes; (void)n_in;
}

// round 4
// speedup vs baseline: 2.1387x; 1.2536x over previous
#include <cuda_runtime.h>
#include <cuda_bf16.h>
#include <cuda_fp16.h>
#include <math.h>
#include <stdint.h>

#define BATCH 64
#define HD    1024
#define ED    1024
#define VOC   32000
#define TT    50
#define G4    (4*HD)
#define START_IDX 1

// ---------------- device scratch ----------------
__device__ __nv_bfloat16 g_emb_hi[VOC*ED];
__device__ __nv_bfloat16 g_emb_lo[VOC*ED];
__device__ __nv_bfloat16 g_Wih_hi[G4*ED];
__device__ __nv_bfloat16 g_Wih_lo[G4*ED];
__device__ __nv_bfloat16 g_Whh_hi[G4*HD];
__device__ __nv_bfloat16 g_Whh_lo[G4*HD];
__device__ __half        g_Wo16[(size_t)VOC*HD];
__device__ __nv_bfloat16 g_hhi[2][BATCH*HD];
__device__ __nv_bfloat16 g_hlo[2][BATCH*HD];
__device__ __half        g_h16[2][BATCH*HD];
__device__ float g_c[BATCH*HD];
__device__ float g_logits[BATCH*VOC];
__device__ int   g_pred[BATCH];

// ---------------- helpers ----------------
__device__ __forceinline__ void mma_bf(float* c, const uint32_t* a, uint32_t b0, uint32_t b1) {
    asm volatile(
        "mma.sync.aligned.m16n8k16.row.col.f32.bf16.bf16.f32 "
        "{%0,%1,%2,%3}, {%4,%5,%6,%7}, {%8,%9}, {%0,%1,%2,%3};\n"
        : "+f"(c[0]), "+f"(c[1]), "+f"(c[2]), "+f"(c[3])
        : "r"(a[0]), "r"(a[1]), "r"(a[2]), "r"(a[3]), "r"(b0), "r"(b1));
}
__device__ __forceinline__ void mma_f16(float* c, const uint32_t* a, uint32_t b0, uint32_t b1) {
    asm volatile(
        "mma.sync.aligned.m16n8k16.row.col.f32.f16.f16.f32 "
        "{%0,%1,%2,%3}, {%4,%5,%6,%7}, {%8,%9}, {%0,%1,%2,%3};\n"
        : "+f"(c[0]), "+f"(c[1]), "+f"(c[2]), "+f"(c[3])
        : "r"(a[0]), "r"(a[1]), "r"(a[2]), "r"(a[3]), "r"(b0), "r"(b1));
}
__device__ __forceinline__ void ldsm4(uint32_t* r, uint32_t addr) {
    asm volatile("ldmatrix.sync.aligned.m8n8.x4.shared.b16 {%0,%1,%2,%3}, [%4];\n"
        : "=r"(r[0]), "=r"(r[1]), "=r"(r[2]), "=r"(r[3]) : "r"(addr));
}
__device__ __forceinline__ void cp16s(uint32_t saddr, const void* g) {
    asm volatile("cp.async.ca.shared.global [%0], [%1], 16;\n" :: "r"(saddr), "l"(g));
}
__device__ __forceinline__ void cp_commit() { asm volatile("cp.async.commit_group;\n" ::: "memory"); }
__device__ __forceinline__ void cp_wait1()  { asm volatile("cp.async.wait_group 1;\n" ::: "memory"); }
__device__ __forceinline__ void cp_wait0()  { asm volatile("cp.async.wait_group 0;\n" ::: "memory"); }

// FMA-only exp. rel err ~1.2e-7 for x<=0.
__device__ __forceinline__ float fast_exp(float x) {
    float t = x * 1.4426950408889634f;
    t = fmaxf(t, -120.0f);
    float n = rintf(t);
    float r = (t - n) * 0.6931471805599453f;
    float p = 1.0f / 5040.0f;
    p = fmaf(p, r, 1.0f / 720.0f);
    p = fmaf(p, r, 1.0f / 120.0f);
    p = fmaf(p, r, 1.0f / 24.0f);
    p = fmaf(p, r, 1.0f / 6.0f);
    p = fmaf(p, r, 0.5f);
    p = fmaf(p, r, 1.0f);
    p = fmaf(p, r, 1.0f);
    float s = __int_as_float(((int)n + 127) << 23);
    return p * s;
}

// ---------------- one-time weight prep ----------------
__global__ void split_kernel(const float* __restrict__ src, int which, int n) {
    int i = blockIdx.x * blockDim.x + threadIdx.x;
    int stride = gridDim.x * blockDim.x;
    if (which == 3) {
        for (; i < n; i += stride) g_Wo16[i] = __float2half(src[i]);
        return;
    }
    __nv_bfloat16 *hi, *lo;
    switch (which) {
        case 0: hi = g_emb_hi; lo = g_emb_lo; break;
        case 1: hi = g_Wih_hi; lo = g_Wih_lo; break;
        default: hi = g_Whh_hi; lo = g_Whh_lo; break;
    }
    for (; i < n; i += stride) {
        float w = src[i];
        __nv_bfloat16 h = __float2bfloat16(w);
        hi[i] = h;
        lo[i] = __float2bfloat16(w - __bfloat162float(h));
    }
}

__global__ void init_kernel(const float* __restrict__ hidden) {
    int i = blockIdx.x * blockDim.x + threadIdx.x;
    if (i < BATCH * HD) {
        float h = hidden[i];
        __nv_bfloat16 hh = __float2bfloat16(h);
        g_hhi[0][i] = hh;
        g_hlo[0][i] = __float2bfloat16(h - __bfloat162float(hh));
        g_c[i] = 0.0f;
    }
    if (i < BATCH) g_pred[i] = START_IDX;
}

// ---------------- K1: gates GEMM + LSTM cell ----------------
// M=64, N=32 (4 gates x 8 units), K=2048, chunk=64, 3-stage cp.async, ldmatrix.
// dyn smem per stage (bytes): Ah 8192 | Al 8192 | Bh 4096 | Bl 4096 -> 24576; x3
__global__ __launch_bounds__(256) void gates_kernel(
        const float* __restrict__ b_ih, const float* __restrict__ b_hh,
        int rd, int wb) {
    extern __shared__ __align__(128) __half dynsm[];
    const uint32_t dynbase = (uint32_t)__cvta_generic_to_shared(dynsm);
    __shared__ float Cs[64][33];
    __shared__ int spred[64];

    const int tid = threadIdx.x;
    const int u0 = blockIdx.x * 8;
    if (tid < 64) spred[tid] = g_pred[tid];
    __syncthreads();

    const int lane = tid & 31, wid = tid >> 5;
    const int gq = lane >> 2, cq = lane & 3;
    const int wm = wid & 3, wn = wid >> 2;   // 4 m-groups x 2 n-groups
    const int lt = lane >> 3, lr = lane & 7; // ldmatrix tile / row-in-tile

    float acc[2][4];
#pragma unroll
    for (int i = 0; i < 2; i++)
#pragma unroll
        for (int j = 0; j < 4; j++) acc[i][j] = 0.0f;

    auto issue = [&](int it, int st) {
        const int k0 = it * 64;
        const uint32_t base = dynbase + (uint32_t)st * 24576u;
#pragma unroll
        for (int l = 0; l < 2; l++) {
            int idx = tid + l * 256;            // 0..511
            int row = idx >> 3, seg = idx & 7;
            int k = k0 + seg * 8;
            uint32_t sw = (uint32_t)(row * 128 + ((seg ^ (row & 7)) << 4));
            const __nv_bfloat16 *sh, *sl;
            if (k < ED) {
                int e = spred[row];
                sh = &g_emb_hi[(size_t)e * ED + k];
                sl = &g_emb_lo[(size_t)e * ED + k];
            } else {
                sh = &g_hhi[rd][row * HD + (k - ED)];
                sl = &g_hlo[rd][row * HD + (k - ED)];
            }
            cp16s(base + sw, sh);
            cp16s(base + 8192u + sw, sl);
        }
        {
            int row = tid >> 3, seg = tid & 7;  // row 0..31
            int k = k0 + seg * 8;
            int rowg = (row >> 3) * HD + u0 + (row & 7);
            uint32_t sw = (uint32_t)(row * 128 + ((seg ^ (row & 7)) << 4));
            const __nv_bfloat16 *wh, *wl;
            if (k < ED) {
                wh = &g_Wih_hi[(size_t)rowg * ED + k];
                wl = &g_Wih_lo[(size_t)rowg * ED + k];
            } else {
                wh = &g_Whh_hi[(size_t)rowg * HD + (k - ED)];
                wl = &g_Whh_lo[(size_t)rowg * HD + (k - ED)];
            }
            cp16s(base + 16384u + sw, wh);
            cp16s(base + 20480u + sw, wl);
        }
    };

    const int NIT = 32;
    issue(0, 0); cp_commit();
    issue(1, 1); cp_commit();

    const int a_row = wm * 16 + ((lt & 1) << 3) + lr;
    const int a_sh  = lt >> 1;
    const uint32_t a_xor7 = (uint32_t)(a_row & 7);

    for (int it = 0; it < NIT; it++) {
        if (it < NIT - 1) cp_wait1(); else cp_wait0();
        __syncthreads();
        if (it + 2 < NIT) { issue(it + 2, (it + 2) % 3); cp_commit(); }

        const uint32_t base = dynbase + (uint32_t)(it % 3) * 24576u;
        const uint32_t Ahb = base, Alb = base + 8192u, Bhb = base + 16384u, Blb = base + 20480u;
        const uint32_t aoff = (uint32_t)(a_row * 128);

#pragma unroll
        for (int ktp = 0; ktp < 2; ktp++) {
            uint32_t h0[4], h1[4], l0[4], l1[4];
            const uint32_t s0 = (uint32_t)((2 * ktp) * 2 + a_sh);
            const uint32_t s1 = (uint32_t)((2 * ktp + 1) * 2 + a_sh);
            ldsm4(h0, Ahb + aoff + ((s0 ^ a_xor7) << 4));
            ldsm4(h1, Ahb + aoff + ((s1 ^ a_xor7) << 4));
            ldsm4(l0, Alb + aoff + ((s0 ^ a_xor7) << 4));
            ldsm4(l1, Alb + aoff + ((s1 ^ a_xor7) << 4));
#pragma unroll
            for (int nt = 0; nt < 2; nt++) {
                const int rowB = wn * 16 + nt * 8 + lr;
                const uint32_t boff = (uint32_t)(rowB * 128 + (((ktp * 4 + lt) ^ lr) << 4));
                uint32_t bh[4], bl[4];
                ldsm4(bh, Bhb + boff);
                ldsm4(bl, Blb + boff);
                mma_bf(acc[nt], h0, bh[0], bh[1]);
                mma_bf(acc[nt], l0, bh[0], bh[1]);
                mma_bf(acc[nt], h0, bl[0], bl[1]);
                mma_bf(acc[nt], h1, bh[2], bh[3]);
                mma_bf(acc[nt], l1, bh[2], bh[3]);
                mma_bf(acc[nt], h1, bl[2], bl[3]);
            }
        }
    }
    __syncthreads();

    {
        const int m0 = wm * 16 + gq;
#pragma unroll
        for (int nt = 0; nt < 2; nt++) {
            const int nc = wn * 16 + nt * 8 + 2 * cq;
            Cs[m0][nc]         = acc[nt][0];
            Cs[m0][nc + 1]     = acc[nt][1];
            Cs[m0 + 8][nc]     = acc[nt][2];
            Cs[m0 + 8][nc + 1] = acc[nt][3];
        }
    }
    __syncthreads();

    for (int r = tid; r < 64 * 8; r += 256) {
        const int b = r >> 3, uu = r & 7;
        const int u = u0 + uu;
        float iv = Cs[b][uu]      + b_ih[u]          + b_hh[u];
        float fv = Cs[b][8 + uu]  + b_ih[HD + u]     + b_hh[HD + u];
        float gv = Cs[b][16 + uu] + b_ih[2 * HD + u] + b_hh[2 * HD + u];
        float ov = Cs[b][24 + uu] + b_ih[3 * HD + u] + b_hh[3 * HD + u];
        float co = g_c[b * HD + u];
        float si = 1.0f / (1.0f + expf(-iv));
        float sf = 1.0f / (1.0f + expf(-fv));
        float so = 1.0f / (1.0f + expf(-ov));
        float cn = sf * co + si * tanhf(gv);
        float hn = so * tanhf(cn);
        g_c[b * HD + u] = cn;
        __nv_bfloat16 hh = __float2bfloat16(hn);
        g_hhi[wb][b * HD + u] = hh;
        g_hlo[wb][b * HD + u] = __float2bfloat16(hn - __bfloat162float(hh));
        g_h16[wb][b * HD + u] = __float2half(hn);
    }
}

// ---------------- K2: logits GEMM 64 x 32000, K=1024, fp16, ldmatrix ----------
// 125 blocks x N=256, chunk 64, 3-stage. dyn smem/stage: A 8192 B | B 32768 B = 40960; x3
__global__ __launch_bounds__(256) void logits_kernel(
        const float* __restrict__ b_out, int rd) {
    extern __shared__ __align__(128) __half dynsm2[];
    const uint32_t dynbase = (uint32_t)__cvta_generic_to_shared(dynsm2);

    const int tid = threadIdx.x;
    const int n0 = blockIdx.x * 256;
    const int lane = tid & 31, wid = tid >> 5;
    const int gq = lane >> 2, cq = lane & 3;
    const int wm = wid & 3, wn = wid >> 2;   // 4 m-groups x 2 n-groups (each 128 cols)
    const int lt = lane >> 3, lr = lane & 7;

    float acc[16][4];
#pragma unroll
    for (int i = 0; i < 16; i++)
#pragma unroll
        for (int j = 0; j < 4; j++) acc[i][j] = 0.0f;

    auto issue = [&](int it, int st) {
        const int k0 = it * 64;
        const uint32_t Ab = dynbase + (uint32_t)st * 40960u;
        const uint32_t Bb = Ab + 8192u;
#pragma unroll
        for (int l = 0; l < 2; l++) {
            int idx = tid + l * 256;
            int row = idx >> 3, seg = idx & 7;
            cp16s(Ab + (uint32_t)(row * 128 + ((seg ^ (row & 7)) << 4)),
                  &g_h16[rd][row * HD + k0 + seg * 8]);
        }
#pragma unroll
        for (int l = 0; l < 8; l++) {
            int idx = tid + l * 256;
            int row = idx >> 3, seg = idx & 7;
            cp16s(Bb + (uint32_t)(row * 128 + ((seg ^ (row & 7)) << 4)),
                  &g_Wo16[(size_t)(n0 + row) * HD + k0 + seg * 8]);
        }
    };

    const int NIT = 16;
    issue(0, 0); cp_commit();
    issue(1, 1); cp_commit();

    const int a_row = wm * 16 + ((lt & 1) << 3) + lr;
    const int a_sh  = lt >> 1;
    const uint32_t a_xor7 = (uint32_t)(a_row & 7);

    for (int it = 0; it < NIT; it++) {
        if (it < NIT - 1) cp_wait1(); else cp_wait0();
        __syncthreads();
        if (it + 2 < NIT) { issue(it + 2, (it + 2) % 3); cp_commit(); }

        const uint32_t Ab = dynbase + (uint32_t)(it % 3) * 40960u;
        const uint32_t Bb = Ab + 8192u;
        const uint32_t aoff = (uint32_t)(a_row * 128);

#pragma unroll
        for (int ktp = 0; ktp < 2; ktp++) {
            uint32_t a0[4], a1[4];
            const uint32_t s0 = (uint32_t)((2 * ktp) * 2 + a_sh);
            const uint32_t s1 = (uint32_t)((2 * ktp + 1) * 2 + a_sh);
            ldsm4(a0, Ab + aoff + ((s0 ^ a_xor7) << 4));
            ldsm4(a1, Ab + aoff + ((s1 ^ a_xor7) << 4));
#pragma unroll
            for (int nt = 0; nt < 16; nt++) {
                const int rowB = wn * 128 + nt * 8 + lr;
                uint32_t b[4];
                ldsm4(b, Bb + (uint32_t)(rowB * 128 + (((ktp * 4 + lt) ^ lr) << 4)));
                mma_f16(acc[nt], a0, b[0], b[1]);
                mma_f16(acc[nt], a1, b[2], b[3]);
            }
        }
    }

    const int m0 = wm * 16 + gq;
#pragma unroll
    for (int nt = 0; nt < 16; nt++) {
        const int nc = n0 + wn * 128 + nt * 8 + 2 * cq;
        float bo0 = b_out[nc], bo1 = b_out[nc + 1];
        float2 v0 = make_float2(acc[nt][0] + bo0, acc[nt][1] + bo1);
        float2 v1 = make_float2(acc[nt][2] + bo0, acc[nt][3] + bo1);
        *(float2*)&g_logits[m0 * VOC + nc]       = v0;
        *(float2*)&g_logits[(m0 + 8) * VOC + nc] = v1;
    }
}

// ---------------- K3: softmax + candidate argmax + exact rescue ----------------
__global__ __launch_bounds__(1024) void softmax_kernel(
        float* __restrict__ out, const float* __restrict__ Wout,
        const float* __restrict__ b_out, int t, int wp, int rd) {
    __shared__ float sm_[1024];
    __shared__ float ss_[1024];
    __shared__ float red[32];
    __shared__ float hbuf[1024];
    __shared__ int cand[64];
    __shared__ int ncand;
    const int b = blockIdx.x;
    const int tid = threadIdx.x;
    const int lane = tid & 31, wid = tid >> 5;
    const float* lrow = g_logits + b * VOC;

    if (tid == 0) ncand = 0;

    float m = -1e30f, s = 0.0f;
    for (int v = tid; v < VOC; v += 1024) {
        float x = lrow[v];
        if (x > m) { s = fmaf(s, fast_exp(m - x), 1.0f); m = x; }
        else s += fast_exp(x - m);
    }
    sm_[tid] = m; ss_[tid] = s;
    __syncthreads();
    for (int st = 512; st > 0; st >>= 1) {
        if (tid < st) {
            float mo = sm_[tid + st], so = ss_[tid + st];
            float mc = sm_[tid],      sc = ss_[tid];
            if (mo > mc) { sm_[tid] = mo; ss_[tid] = fmaf(sc, fast_exp(mc - mo), so); }
            else         { ss_[tid] = fmaf(so, fast_exp(mo - mc), sc); }
        }
        __syncthreads();
    }
    const float M = sm_[0];
    const float inv = 1.0f / ss_[0];
    const float thresh = M - 0.01f;
    __syncthreads();

    float* orow = out + (size_t)b * TT * VOC + (size_t)t * VOC;
    for (int v = tid; v < VOC; v += 1024) {
        float x = __ldcs(&lrow[v]);
        __stcs(&orow[v], fast_exp(x - M) * inv);
        if (x > thresh) {
            int p = atomicAdd(&ncand, 1);
            if (p < 64) cand[p] = v;
        }
    }

    hbuf[tid] = __bfloat162float(g_hhi[rd][b * HD + tid]) +
                __bfloat162float(g_hlo[rd][b * HD + tid]);
    __syncthreads();

    const int nc = min(ncand, 64);
    float bestv = -1e30f;
    int   besti = VOC;
    for (int i = 0; i < nc; i++) {
        const int v = cand[i];
        float part = hbuf[tid] * Wout[(size_t)v * HD + tid];
#pragma unroll
        for (int o = 16; o > 0; o >>= 1) part += __shfl_xor_sync(0xFFFFFFFFu, part, o);
        if (lane == 0) red[wid] = part;
        __syncthreads();
        if (tid < 32) {
            float pv = red[tid];
#pragma unroll
            for (int o = 16; o > 0; o >>= 1) pv += __shfl_xor_sync(0xFFFFFFFFu, pv, o);
            if (tid == 0) {
                float lg = pv + b_out[v];
                if (lg > bestv || (lg == bestv && v < besti)) { bestv = lg; besti = v; }
            }
        }
        __syncthreads();
    }

    if (tid == 0) {
        g_pred[b] = besti;
        if (wp) out[(size_t)BATCH * TT * VOC + (size_t)b * TT + t] = (float)besti;
    }
}

// ---------------- launch ----------------
extern "C" void kernel_launch(void* const* d_in, const int* in_sizes, int n_in,
                              void* d_out, int out_size) {
    const float* hidden = (const float*)d_in[0];
    const float* emb    = (const float*)d_in[1];
    const float* W_ih   = (const float*)d_in[2];
    const float* W_hh   = (const float*)d_in[3];
    const float* b_ih   = (const float*)d_in[4];
    const float* b_hh   = (const float*)d_in[5];
    const float* W_out  = (const float*)d_in[6];
    const float* b_out  = (const float*)d_in[7];
    float* out = (float*)d_out;
    const long long need_pred = (long long)BATCH * TT * VOC + (long long)BATCH * TT;
    int wp = ((long long)out_size >= need_pred) ? 1 : 0;

    static int attr_done = 0;
    cudaFuncSetAttribute(gates_kernel,  cudaFuncAttributeMaxDynamicSharedMemorySize, 3 * 24576);
    cudaFuncSetAttribute(logits_kernel, cudaFuncAttributeMaxDynamicSharedMemorySize, 3 * 40960);
    (void)attr_done;

    init_kernel<<<(BATCH * HD + 255) / 256, 256>>>(hidden);
    split_kernel<<<4096, 256>>>(emb,   0, VOC * ED);
    split_kernel<<<2048, 256>>>(W_ih,  1, G4 * ED);
    split_kernel<<<2048, 256>>>(W_hh,  2, G4 * HD);
    split_kernel<<<4096, 256>>>(W_out, 3, VOC * HD);

    for (int t = 0; t < TT; t++) {
        const int rd = t & 1;
        const int wb = rd ^ 1;
        gates_kernel<<<128, 256, 3 * 24576>>>(b_ih, b_hh, rd, wb);
        logits_kernel<<<125, 256, 3 * 40960>>>(b_out, wb);
        softmax_kernel<<<BATCH, 1024>>>(out, W_out, b_out, t, wp, wb);
    }
    (void)in_sizes; (void)n_in;
}